// round 14
// baseline (speedup 1.0000x reference)
#include <cuda_runtime.h>
#include <cuda_bf16.h>
#include <math_constants.h>
#include <cstdint>

#define B_   1024
#define L_   50
#define D_   256
#define D2_  512
#define DEG_ 12
#define BL_  (B_ * L_)   // 51200
#define GM_  40000       // number of graph nodes

// ---------------- scratch (device globals; no allocations allowed) ----------
__device__ __align__(16) float g_t2[B_ * D_];
__device__ __align__(16) __nv_bfloat16 g_a_hi[(size_t)GM_ * D_];   // graph_embs hi
__device__ __align__(16) __nv_bfloat16 g_a_lo[(size_t)GM_ * D_];   // graph_embs lo
__device__ __align__(16) float g_G1[(size_t)GM_ * D_];             // graph_embs @ W1
__device__ __align__(16) __nv_bfloat16 g_w1t_hi[D_ * D_];          // W1^T hi [n][k]
__device__ __align__(16) __nv_bfloat16 g_w1t_lo[D_ * D_];          // W1^T lo [n][k]
__device__ __align__(16) __nv_bfloat16 g_tg_hi[B_ * D2_];          // tgt hi [b][k]
__device__ __align__(16) __nv_bfloat16 g_tg_lo[B_ * D2_];          // tgt lo
__device__ __align__(16) __nv_bfloat16 g_wc_hi[D_ * D2_];          // Wc^T hi [n][k]
__device__ __align__(16) __nv_bfloat16 g_wc_lo[D_ * D2_];          // Wc^T lo
__device__ __align__(16) float g_va[D2_];                          // wfw^T @ aw
__device__ __align__(16) float g_bias2[D_];                        // wfb@w2 + at_bias
__device__ float g_ba;                                             // wfb.aw + ab

// ---------------- small helpers ---------------------------------------------
__device__ __forceinline__ float wredsum(float v) {
#pragma unroll
    for (int o = 16; o > 0; o >>= 1) v += __shfl_xor_sync(0xFFFFFFFFu, v, o);
    return v;
}
__device__ __forceinline__ float wredmax(float v) {
#pragma unroll
    for (int o = 16; o > 0; o >>= 1) v = fmaxf(v, __shfl_xor_sync(0xFFFFFFFFu, v, o));
    return v;
}
__device__ __forceinline__ uint32_t smem_u32(const void* p) {
    uint32_t a;
    asm("{ .reg .u64 t; cvta.to.shared.u64 t, %1; cvt.u32.u64 %0, t; }" : "=r"(a) : "l"(p));
    return a;
}
__device__ __forceinline__ uint32_t pk2(__nv_bfloat16 a, __nv_bfloat16 b) {
    __nv_bfloat162 p(a, b);
    return *(uint32_t*)&p;
}
__device__ __forceinline__ void split4(float4 v, uint2& hi, uint2& lo) {
    __nv_bfloat16 h0 = __float2bfloat16(v.x), h1 = __float2bfloat16(v.y);
    __nv_bfloat16 h2 = __float2bfloat16(v.z), h3 = __float2bfloat16(v.w);
    __nv_bfloat16 l0 = __float2bfloat16(v.x - __bfloat162float(h0));
    __nv_bfloat16 l1 = __float2bfloat16(v.y - __bfloat162float(h1));
    __nv_bfloat16 l2 = __float2bfloat16(v.z - __bfloat162float(h2));
    __nv_bfloat16 l3 = __float2bfloat16(v.w - __bfloat162float(h3));
    hi = make_uint2(pk2(h0, h1), pk2(h2, h3));
    lo = make_uint2(pk2(l0, l1), pk2(l2, l3));
}
__device__ __forceinline__ void cpa16(uint32_t dst, const void* src) {
    asm volatile("cp.async.cg.shared.global [%0], [%1], 16;" :: "r"(dst), "l"(src));
}
__device__ __forceinline__ void ldsm4(uint32_t* r, uint32_t addr) {
    asm volatile("ldmatrix.sync.aligned.m8n8.x4.shared.b16 {%0,%1,%2,%3}, [%4];"
                 : "=r"(r[0]), "=r"(r[1]), "=r"(r[2]), "=r"(r[3]) : "r"(addr));
}
__device__ __forceinline__ void mma_bf16(float* c, const uint32_t* a, uint32_t b0, uint32_t b1) {
    asm volatile(
        "mma.sync.aligned.m16n8k16.row.col.f32.bf16.bf16.f32 "
        "{%0,%1,%2,%3}, {%4,%5,%6,%7}, {%8,%9}, {%0,%1,%2,%3};"
        : "+f"(c[0]), "+f"(c[1]), "+f"(c[2]), "+f"(c[3])
        : "r"(a[0]), "r"(a[1]), "r"(a[2]), "r"(a[3]), "r"(b0), "r"(b1));
}
// fast z^inv for z >= 0 (lg2(0) = -inf -> ex2(-inf) = 0, matching max(z,0)^inv)
__device__ __forceinline__ float fpow(float z, float inv) {
    z = fmaxf(z, 0.f);
    float l, r;
    asm("lg2.approx.f32 %0, %1;" : "=f"(l) : "f"(z));
    l *= inv;
    asm("ex2.approx.f32 %0, %1;" : "=f"(r) : "f"(l));
    return r;
}

// ---------------- K0a: prep1 — w1 split + tgt split (pure copies) -----------
#define P1_TGT 256   // [0,256) w1 | [256,768) tgt

__global__ void k_prep1(const float* __restrict__ w1, const float* __restrict__ tgt) {
    int bid = blockIdx.x;
    int tid = threadIdx.x;
    if (bid < P1_TGT) {
        int f = bid * 256 + tid;  // 65536 total
        float a = w1[f];
        int k = f >> 8, n = f & 255;
        __nv_bfloat16 h = __float2bfloat16(a);
        float lo = a - __bfloat162float(h);
        g_w1t_hi[n * 256 + k] = h;
        g_w1t_lo[n * 256 + k] = __float2bfloat16(lo);
    } else {
        int f4 = ((bid - P1_TGT) * 256 + tid) * 4;
        float4 v = *(const float4*)&tgt[f4];
        uint2 hi, lo;
        split4(v, hi, lo);
        *(uint2*)&g_tg_hi[f4] = hi;
        *(uint2*)&g_tg_lo[f4] = lo;
    }
}

// ---------------- K0b: prep2 — Wc (+va) and bias2 (+ba) ---------------------
#define P2_B2 64     // [0,64) Wc+va (8 k each) | 64 bias2+ba

__global__ void k_prep2(const float* __restrict__ w2, const float* __restrict__ wfw,
                        const float* __restrict__ wfb, const float* __restrict__ aw,
                        const float* __restrict__ ab, const float* __restrict__ atb) {
    int bid = blockIdx.x;
    int tid = threadIdx.x;
    int lane = tid & 31, w = tid >> 5;

    if (bid < P2_B2) {
        int k0 = bid * 8;
        __shared__ float s_wf[8][256];   // s_wf[j][d] = wfw[d][k0+j]
        {
            float4 a = *(const float4*)&wfw[(size_t)tid * D2_ + k0];
            float4 b = *(const float4*)&wfw[(size_t)tid * D2_ + k0 + 4];
            s_wf[0][tid] = a.x; s_wf[1][tid] = a.y;
            s_wf[2][tid] = a.z; s_wf[3][tid] = a.w;
            s_wf[4][tid] = b.x; s_wf[5][tid] = b.y;
            s_wf[6][tid] = b.z; s_wf[7][tid] = b.w;
        }
        __syncthreads();
        float acc[8];
#pragma unroll
        for (int j = 0; j < 8; j++) acc[j] = 0.f;
#pragma unroll 4
        for (int d = 0; d < 256; d++) {
            float wv = w2[(size_t)d * D_ + tid];
#pragma unroll
            for (int j = 0; j < 8; j++) acc[j] += s_wf[j][d] * wv;
        }
#pragma unroll
        for (int j = 0; j < 8; j++) {
            __nv_bfloat16 h = __float2bfloat16(acc[j]);
            float lo = acc[j] - __bfloat162float(h);
            g_wc_hi[(size_t)tid * D2_ + k0 + j] = h;
            g_wc_lo[(size_t)tid * D2_ + k0 + j] = __float2bfloat16(lo);
        }
        if (w == 0) {
#pragma unroll
            for (int j = 0; j < 8; j++) {
                float p = 0.f;
#pragma unroll
                for (int i = 0; i < 8; i++)
                    p += s_wf[j][lane * 8 + i] * __ldg(&aw[lane * 8 + i]);
                p = wredsum(p);
                if (lane == 0) g_va[k0 + j] = p;
            }
        }
    } else {
        __shared__ float s_b[256];
        __shared__ float s_part[8];
        s_b[tid] = wfb[tid];
        __syncthreads();
        float acc = 0.f;
#pragma unroll 4
        for (int d = 0; d < 256; d++) acc += s_b[d] * w2[(size_t)d * D_ + tid];
        g_bias2[tid] = acc + atb[tid];
        float p = wredsum(s_b[tid] * __ldg(&aw[tid]));
        if (lane == 0) s_part[w] = p;
        __syncthreads();
        if (tid < 32) {
            float t = (tid < 8) ? s_part[tid] : 0.f;
            t = wredsum(t);
            if (tid == 0) g_ba = t + ab[0];
        }
    }
}

// ---------------- K1: graph conv (lean: 32 regs, high occupancy) ------------
__global__ void k_gconv(const float* __restrict__ emb, const int* __restrict__ cols,
                        const float* __restrict__ vals) {
    int tid = threadIdx.x;
    int node = blockIdx.x * 4 + (tid >> 6);
    int d4 = (tid & 63) << 2;
    float4 h = *(const float4*)&emb[(size_t)node * D_ + d4];
    int base = node * DEG_;
#pragma unroll
    for (int j = 0; j < DEG_; j++) {
        int c = __ldg(&cols[base + j]);
        float v = __ldg(&vals[base + j]);
        float4 e = *(const float4*)&emb[(size_t)c * D_ + d4];
        h.x += v * e.x;
        h.y += v * e.y;
        h.z += v * e.z;
        h.w += v * e.w;
    }
    h.x *= 0.5f; h.y *= 0.5f; h.z *= 0.5f; h.w *= 0.5f;
    size_t off = (size_t)node * D_ + d4;
    uint2 hi, lo;
    split4(h, hi, lo);
    *(uint2*)&g_a_hi[off] = hi;
    *(uint2*)&g_a_lo[off] = lo;
}

// ---------------- K2: GEMMs: G1 = gemb @ W1 (1250 blks) + t2 = tgt@Wc (32) --
#define GEMM_SMEM 98304
#define BUF_STRIDE 49152
#define GEMM_BLKS 1250
#define T2_BLKS 32

__device__ __forceinline__ void load_chunk(uint32_t sb, int tid, int row0, int n0, int kc,
                                           const __nv_bfloat16* __restrict__ Ah,
                                           const __nv_bfloat16* __restrict__ Al,
                                           const __nv_bfloat16* __restrict__ Bh,
                                           const __nv_bfloat16* __restrict__ Bl,
                                           int lda, int ldb) {
#pragma unroll
    for (int i = 0; i < 2; i++) {
        int idx = tid + i * 256;
        int r = idx >> 3, g = idx & 7;
        uint32_t soff = (uint32_t)(r * 128 + ((g ^ (r & 7)) << 4));
        size_t abase = (size_t)(row0 + r) * lda + kc * 64 + g * 8;
        cpa16(sb + soff,        Ah + abase);
        cpa16(sb + 8192 + soff, Al + abase);
    }
#pragma unroll
    for (int i = 0; i < 4; i++) {
        int idx = tid + i * 256;
        int r = idx >> 3, g = idx & 7;
        uint32_t soff = (uint32_t)(r * 128 + ((g ^ (r & 7)) << 4));
        size_t bbase = (size_t)(n0 + r) * ldb + kc * 64 + g * 8;
        cpa16(sb + 16384 + soff, Bh + bbase);
        cpa16(sb + 32768 + soff, Bl + bbase);
    }
    asm volatile("cp.async.commit_group;" ::: "memory");
}

__global__ __launch_bounds__(256, 2) void k_gemm() {
    extern __shared__ char sm[];
    uint32_t sbase = smem_u32(sm);
    int tid = threadIdx.x, lane = tid & 31, w = tid >> 5;
    int bid = blockIdx.x;

    const __nv_bfloat16 *Ah, *Al, *Bh, *Bl;
    int lda, ldb, nkc, row0, n0, isT2;
    if (bid < GEMM_BLKS) {
        Ah = g_a_hi; Al = g_a_lo; Bh = g_w1t_hi; Bl = g_w1t_lo;
        lda = 256; ldb = 256; nkc = 4; isT2 = 0;
        row0 = (bid >> 1) * 64; n0 = (bid & 1) * 128;
    } else {
        int t = bid - GEMM_BLKS;
        Ah = g_tg_hi; Al = g_tg_lo; Bh = g_wc_hi; Bl = g_wc_lo;
        lda = 512; ldb = 512; nkc = 8; isT2 = 1;
        row0 = (t >> 1) * 64; n0 = (t & 1) * 128;
    }

    int wm = w & 1, wn = w >> 1;          // 2m x 4n warps; warp tile 32m x 32n
    int quad = lane >> 3, ri = lane & 7;
    int arow_b = wm * 32 + ((quad & 1) << 3) + ri;
    int brow_b = wn * 32 + ((quad & 1) << 3) + ri;
    int gsel = quad >> 1;

    float acc[2][4][4];
#pragma unroll
    for (int i = 0; i < 2; i++)
#pragma unroll
        for (int j = 0; j < 4; j++)
#pragma unroll
            for (int q = 0; q < 4; q++) acc[i][j][q] = 0.f;

    load_chunk(sbase, tid, row0, n0, 0, Ah, Al, Bh, Bl, lda, ldb);

    for (int kc = 0; kc < nkc; kc++) {
        uint32_t sb = sbase + (kc & 1) * BUF_STRIDE;
        asm volatile("cp.async.wait_group 0;" ::: "memory");
        __syncthreads();
        if (kc < nkc - 1)
            load_chunk(sbase + ((kc + 1) & 1) * BUF_STRIDE, tid, row0, n0, kc + 1,
                       Ah, Al, Bh, Bl, lda, ldb);
#pragma unroll
        for (int ks = 0; ks < 4; ks++) {
            uint32_t ah[2][4], al[2][4], bh[2][4], bl[2][4];
            int gx = ((ks * 2 + gsel) ^ ri) << 4;
#pragma unroll
            for (int mt = 0; mt < 2; mt++) {
                uint32_t off = (uint32_t)((arow_b + mt * 16) * 128 + gx);
                ldsm4(ah[mt], sb + off);
                ldsm4(al[mt], sb + 8192 + off);
            }
#pragma unroll
            for (int pt = 0; pt < 2; pt++) {
                uint32_t off = (uint32_t)((brow_b + pt * 16) * 128 + gx);
                ldsm4(bh[pt], sb + 16384 + off);
                ldsm4(bl[pt], sb + 32768 + off);
            }
#pragma unroll
            for (int mt = 0; mt < 2; mt++) {
#pragma unroll
                for (int nt = 0; nt < 4; nt++) {
                    uint32_t b0h = bh[nt >> 1][nt & 1], b1h = bh[nt >> 1][(nt & 1) + 2];
                    uint32_t b0l = bl[nt >> 1][nt & 1], b1l = bl[nt >> 1][(nt & 1) + 2];
                    mma_bf16(acc[mt][nt], ah[mt], b0h, b1h);
                    mma_bf16(acc[mt][nt], ah[mt], b0l, b1l);
                    mma_bf16(acc[mt][nt], al[mt], b0h, b1h);
                }
            }
        }
    }

    int mrb = row0 + wm * 32 + (lane >> 2);
    int ncb = n0 + wn * 32 + (lane & 3) * 2;
    float* outp = isT2 ? g_t2 : g_G1;
#pragma unroll
    for (int mt = 0; mt < 2; mt++) {
#pragma unroll
        for (int nt = 0; nt < 4; nt++) {
            int m = mrb + mt * 16;
            int n = ncb + nt * 8;
            float2 v0 = make_float2(acc[mt][nt][0], acc[mt][nt][1]);
            float2 v1 = make_float2(acc[mt][nt][2], acc[mt][nt][3]);
            if (isT2) {
                float b0 = g_bias2[n], b1 = g_bias2[n + 1];
                v0.x += b0; v0.y += b1;
                v1.x += b0; v1.y += b1;
            }
            *(float2*)&outp[(size_t)m * D_ + n] = v0;
            *(float2*)&outp[(size_t)(m + 8) * D_ + n] = v1;
        }
    }
}

// ---------------- K3: fused scores + alpha + entmax + output ---------------
// dynamic smem: hi rows [32][256] bf16 (16384 B) | lo rows (16384 B) = 32KB
#define PF_ROWS 32
#define FIN_SMEM (2 * PF_ROWS * D_ * 2)
#define BIS_ITERS 34

__global__ __launch_bounds__(256) void k_final(const int* __restrict__ items,
                                               const float* __restrict__ w0,
                                               const float* __restrict__ tgt,
                                               float* __restrict__ out) {
    extern __shared__ __align__(16) char smd[];
    __shared__ __align__(16) float s_t2[256], s_w0[256];
    __shared__ float s_sc[64], s_attn[64];
    __shared__ int s_it[64];
    __shared__ float rs[8];
    int tid = threadIdx.x, lane = tid & 31, w = tid >> 5;
    int b = blockIdx.x;

    s_t2[tid] = g_t2[(size_t)b * D_ + tid];
    s_w0[tid] = w0[tid];
    if (tid < L_) s_it[tid] = items[b * L_ + tid];
    __syncthreads();

    // prefetch first PF_ROWS gemb hi/lo rows (overlaps scores + entmax)
    uint32_t sdm = smem_u32(smd);
    for (int l = w; l < PF_ROWS; l += 8) {
        int it = s_it[l];
        cpa16(sdm + l * 512 + lane * 16,         g_a_hi + (size_t)it * D_ + lane * 8);
        cpa16(sdm + 16384 + l * 512 + lane * 16, g_a_lo + (size_t)it * D_ + lane * 8);
    }
    asm volatile("cp.async.commit_group;" ::: "memory");

    // scores: warp per row-pair (l, l+8) for 2x memory-level parallelism
    float4 t0 = *(const float4*)&s_t2[lane * 8], t1 = *(const float4*)&s_t2[lane * 8 + 4];
    float4 w0a = *(const float4*)&s_w0[lane * 8], w0b = *(const float4*)&s_w0[lane * 8 + 4];
#pragma unroll
    for (int p = 0; p < 4; p++) {
        int l0 = w + p * 16;
        if (l0 >= L_) break;
        int l1 = l0 + 8;
        bool h1 = l1 < L_;
        const float* gp0 = g_G1 + (size_t)s_it[l0] * D_ + lane * 8;
        const float* gp1 = g_G1 + (size_t)s_it[h1 ? l1 : l0] * D_ + lane * 8;
        float4 a0 = *(const float4*)gp0, a1 = *(const float4*)(gp0 + 4);
        float4 c0 = *(const float4*)gp1, c1 = *(const float4*)(gp1 + 4);
        float acc0 = fmaxf(a0.x + t0.x, 0.f) * w0a.x + fmaxf(a0.y + t0.y, 0.f) * w0a.y +
                     fmaxf(a0.z + t0.z, 0.f) * w0a.z + fmaxf(a0.w + t0.w, 0.f) * w0a.w +
                     fmaxf(a1.x + t1.x, 0.f) * w0b.x + fmaxf(a1.y + t1.y, 0.f) * w0b.y +
                     fmaxf(a1.z + t1.z, 0.f) * w0b.z + fmaxf(a1.w + t1.w, 0.f) * w0b.w;
        float acc1 = fmaxf(c0.x + t0.x, 0.f) * w0a.x + fmaxf(c0.y + t0.y, 0.f) * w0a.y +
                     fmaxf(c0.z + t0.z, 0.f) * w0a.z + fmaxf(c0.w + t0.w, 0.f) * w0a.w +
                     fmaxf(c1.x + t1.x, 0.f) * w0b.x + fmaxf(c1.y + t1.y, 0.f) * w0b.y +
                     fmaxf(c1.z + t1.z, 0.f) * w0b.z + fmaxf(c1.w + t1.w, 0.f) * w0b.w;
        acc0 = wredsum(acc0);
        acc1 = wredsum(acc1);
        if (lane == 0) {
            s_sc[l0] = acc0;
            if (h1) s_sc[l1] = acc1;
        }
    }
    __syncthreads();

    // warp 0: alpha = sigmoid(tgt.va + ba) + 1, then entmax bisection
    if (w == 0) {
        float av = 0.f;
        const float* tp = tgt + (size_t)b * D2_ + lane * 16;
        const float* vp = g_va + lane * 16;
#pragma unroll
        for (int i = 0; i < 4; i++) {
            float4 tv = *(const float4*)(tp + i * 4);
            float4 vv = *(const float4*)(vp + i * 4);
            av += tv.x * vv.x + tv.y * vv.y + tv.z * vv.z + tv.w * vv.w;
        }
        av = wredsum(av);
        float x = av + g_ba;
        float alpha = 1.f / (1.f + expf(-x)) + 1.f;
        if (alpha == 1.f) alpha = 1.00001f;

        float am1 = alpha - 1.f;
        float inv = 1.f / am1;
        float Xa0 = s_sc[lane] * am1;
        float Xa1 = (lane < L_ - 32) ? s_sc[32 + lane] * am1 : -CUDART_INF_F;

        float m = wredmax(fmaxf(Xa0, Xa1));
        float tau_lo = m - 1.f;
        float tau_hi = m - powf(1.f / (float)L_, am1);
        float f_lo = wredsum(fpow(Xa0 - tau_lo, inv) + fpow(Xa1 - tau_lo, inv)) - 1.f;

        float dm = tau_hi - tau_lo;
        float tau_m = tau_lo;
        for (int it = 0; it < BIS_ITERS; it++) {
            dm *= 0.5f;
            tau_m = tau_lo + dm;
            float fm = wredsum(fpow(Xa0 - tau_m, inv) + fpow(Xa1 - tau_m, inv)) - 1.f;
            if (fm * f_lo >= 0.f) tau_lo = tau_m;
        }
        float p0 = fpow(Xa0 - tau_m, inv);
        float p1 = fpow(Xa1 - tau_m, inv);
        float s = wredsum(p0 + p1);
        s_attn[lane] = p0 / s;
        if (lane < L_ - 32) s_attn[32 + lane] = p1 / s;
    }
    asm volatile("cp.async.wait_group 0;" ::: "memory");
    __syncthreads();

    // output: c = attn^T (hi+lo); first PF_ROWS from smem, rest direct
    const __nv_bfloat16* ph = (const __nv_bfloat16*)smd;
    const __nv_bfloat16* pl = (const __nv_bfloat16*)(smd + 16384);
    float accd = 0.f;
#pragma unroll
    for (int l = 0; l < PF_ROWS; l++) {
        float v = __bfloat162float(ph[l * 256 + tid]) + __bfloat162float(pl[l * 256 + tid]);
        accd += s_attn[l] * v;
    }
#pragma unroll 6
    for (int l = PF_ROWS; l < L_; l++) {
        int it = s_it[l];
        float v = __bfloat162float(__ldg(&g_a_hi[(size_t)it * D_ + tid])) +
                  __bfloat162float(__ldg(&g_a_lo[(size_t)it * D_ + tid]));
        accd += s_attn[l] * v;
    }
    const float SC = 1.0507009873554805f;
    const float AL = 1.6732632423543772f;
    float v = accd > 0.f ? SC * accd : SC * AL * expm1f(accd);
    float sq = wredsum(v * v);
    if (lane == 0) rs[w] = sq;
    __syncthreads();
    if (tid < 32) {
        float t = (tid < 8) ? rs[tid] : 0.f;
        t = wredsum(t);
        if (tid == 0) rs[0] = t;
    }
    __syncthreads();
    out[(size_t)b * D_ + tid] = v / sqrtf(rs[0]);
}

// ---------------- launch ------------------------------------------------------
extern "C" void kernel_launch(void* const* d_in, const int* in_sizes, int n_in,
                              void* d_out, int out_size) {
    const int* items = (const int*)d_in[0];
    const float* tgt = (const float*)d_in[3];
    const float* emb = (const float*)d_in[4];
    const int* acols = (const int*)d_in[6];
    const float* avals = (const float*)d_in[7];
    const float* wfw = (const float*)d_in[8];
    const float* wfb = (const float*)d_in[9];
    const float* aww = (const float*)d_in[10];
    const float* awb = (const float*)d_in[11];
    const float* w0 = (const float*)d_in[12];
    const float* w1 = (const float*)d_in[13];
    const float* w2 = (const float*)d_in[14];
    const float* abias = (const float*)d_in[15];
    float* out = (float*)d_out;

    cudaFuncSetAttribute(k_gemm, cudaFuncAttributeMaxDynamicSharedMemorySize, GEMM_SMEM);
    cudaFuncSetAttribute(k_final, cudaFuncAttributeMaxDynamicSharedMemorySize, FIN_SMEM);

    // 5 launches; ncu captures launch index 3 -> k_gemm this round
    k_prep1<<<768, 256>>>(w1, tgt);
    k_prep2<<<P2_B2 + 1, 256>>>(w2, wfw, wfb, aww, awb, abias);
    k_gconv<<<GM_ / 4, 256>>>(emb, acols, avals);
    k_gemm<<<GEMM_BLKS + T2_BLKS, 256, GEMM_SMEM>>>();
    k_final<<<B_, 256, FIN_SMEM>>>(items, w0, tgt, out);
}

// round 15
// speedup vs baseline: 1.0287x; 1.0287x over previous
#include <cuda_runtime.h>
#include <cuda_bf16.h>
#include <math_constants.h>
#include <cstdint>

#define B_   1024
#define L_   50
#define D_   256
#define D2_  512
#define DEG_ 12
#define BL_  (B_ * L_)   // 51200
#define GM_  40000       // number of graph nodes

// ---------------- scratch (device globals; no allocations allowed) ----------
__device__ __align__(16) float g_t2[B_ * D_];
__device__ __align__(16) __nv_bfloat16 g_a_hi[(size_t)GM_ * D_];   // graph_embs hi
__device__ __align__(16) __nv_bfloat16 g_a_lo[(size_t)GM_ * D_];   // graph_embs lo
__device__ __align__(16) float g_G1[(size_t)GM_ * D_];             // graph_embs @ W1
__device__ __align__(16) __nv_bfloat16 g_w1t_hi[D_ * D_];          // W1^T hi [n][k]
__device__ __align__(16) __nv_bfloat16 g_w1t_lo[D_ * D_];          // W1^T lo [n][k]
__device__ __align__(16) __nv_bfloat16 g_tg_hi[B_ * D2_];          // tgt hi [b][k]
__device__ __align__(16) __nv_bfloat16 g_tg_lo[B_ * D2_];          // tgt lo
__device__ __align__(16) __nv_bfloat16 g_wc_hi[D_ * D2_];          // Wc^T hi [n][k]
__device__ __align__(16) __nv_bfloat16 g_wc_lo[D_ * D2_];          // Wc^T lo
__device__ __align__(16) float g_va[D2_];                          // wfw^T @ aw
__device__ __align__(16) float g_bias2[D_];                        // wfb@w2 + at_bias
__device__ float g_ba;                                             // wfb.aw + ab

// ---------------- small helpers ---------------------------------------------
__device__ __forceinline__ float wredsum(float v) {
#pragma unroll
    for (int o = 16; o > 0; o >>= 1) v += __shfl_xor_sync(0xFFFFFFFFu, v, o);
    return v;
}
__device__ __forceinline__ float wredmax(float v) {
#pragma unroll
    for (int o = 16; o > 0; o >>= 1) v = fmaxf(v, __shfl_xor_sync(0xFFFFFFFFu, v, o));
    return v;
}
__device__ __forceinline__ uint32_t smem_u32(const void* p) {
    uint32_t a;
    asm("{ .reg .u64 t; cvta.to.shared.u64 t, %1; cvt.u32.u64 %0, t; }" : "=r"(a) : "l"(p));
    return a;
}
__device__ __forceinline__ uint32_t pk2(__nv_bfloat16 a, __nv_bfloat16 b) {
    __nv_bfloat162 p(a, b);
    return *(uint32_t*)&p;
}
__device__ __forceinline__ void split4(float4 v, uint2& hi, uint2& lo) {
    __nv_bfloat16 h0 = __float2bfloat16(v.x), h1 = __float2bfloat16(v.y);
    __nv_bfloat16 h2 = __float2bfloat16(v.z), h3 = __float2bfloat16(v.w);
    __nv_bfloat16 l0 = __float2bfloat16(v.x - __bfloat162float(h0));
    __nv_bfloat16 l1 = __float2bfloat16(v.y - __bfloat162float(h1));
    __nv_bfloat16 l2 = __float2bfloat16(v.z - __bfloat162float(h2));
    __nv_bfloat16 l3 = __float2bfloat16(v.w - __bfloat162float(h3));
    hi = make_uint2(pk2(h0, h1), pk2(h2, h3));
    lo = make_uint2(pk2(l0, l1), pk2(l2, l3));
}
__device__ __forceinline__ void cpa16(uint32_t dst, const void* src) {
    asm volatile("cp.async.cg.shared.global [%0], [%1], 16;" :: "r"(dst), "l"(src));
}
__device__ __forceinline__ void ldsm4(uint32_t* r, uint32_t addr) {
    asm volatile("ldmatrix.sync.aligned.m8n8.x4.shared.b16 {%0,%1,%2,%3}, [%4];"
                 : "=r"(r[0]), "=r"(r[1]), "=r"(r[2]), "=r"(r[3]) : "r"(addr));
}
__device__ __forceinline__ void mma_bf16(float* c, const uint32_t* a, uint32_t b0, uint32_t b1) {
    asm volatile(
        "mma.sync.aligned.m16n8k16.row.col.f32.bf16.bf16.f32 "
        "{%0,%1,%2,%3}, {%4,%5,%6,%7}, {%8,%9}, {%0,%1,%2,%3};"
        : "+f"(c[0]), "+f"(c[1]), "+f"(c[2]), "+f"(c[3])
        : "r"(a[0]), "r"(a[1]), "r"(a[2]), "r"(a[3]), "r"(b0), "r"(b1));
}
// fast z^inv for z >= 0 (lg2(0) = -inf -> ex2(-inf) = 0, matching max(z,0)^inv)
__device__ __forceinline__ float fpow(float z, float inv) {
    z = fmaxf(z, 0.f);
    float l, r;
    asm("lg2.approx.f32 %0, %1;" : "=f"(l) : "f"(z));
    l *= inv;
    asm("ex2.approx.f32 %0, %1;" : "=f"(r) : "f"(l));
    return r;
}

// ---------------- K0: prep2 — Wc (+va) and bias2 (+ba), 65 blocks -----------
#define P2_B2 64     // [0,64) Wc+va (8 k each) | 64 bias2+ba

__global__ void k_prep2(const float* __restrict__ w2, const float* __restrict__ wfw,
                        const float* __restrict__ wfb, const float* __restrict__ aw,
                        const float* __restrict__ ab, const float* __restrict__ atb) {
    int bid = blockIdx.x;
    int tid = threadIdx.x;
    int lane = tid & 31, w = tid >> 5;

    if (bid < P2_B2) {
        int k0 = bid * 8;
        __shared__ float s_wf[8][256];   // s_wf[j][d] = wfw[d][k0+j]
        {
            float4 a = *(const float4*)&wfw[(size_t)tid * D2_ + k0];
            float4 b = *(const float4*)&wfw[(size_t)tid * D2_ + k0 + 4];
            s_wf[0][tid] = a.x; s_wf[1][tid] = a.y;
            s_wf[2][tid] = a.z; s_wf[3][tid] = a.w;
            s_wf[4][tid] = b.x; s_wf[5][tid] = b.y;
            s_wf[6][tid] = b.z; s_wf[7][tid] = b.w;
        }
        __syncthreads();
        float acc[8];
#pragma unroll
        for (int j = 0; j < 8; j++) acc[j] = 0.f;
#pragma unroll 4
        for (int d = 0; d < 256; d++) {
            float wv = w2[(size_t)d * D_ + tid];
#pragma unroll
            for (int j = 0; j < 8; j++) acc[j] += s_wf[j][d] * wv;
        }
#pragma unroll
        for (int j = 0; j < 8; j++) {
            __nv_bfloat16 h = __float2bfloat16(acc[j]);
            float lo = acc[j] - __bfloat162float(h);
            g_wc_hi[(size_t)tid * D2_ + k0 + j] = h;
            g_wc_lo[(size_t)tid * D2_ + k0 + j] = __float2bfloat16(lo);
        }
        if (w == 0) {
#pragma unroll
            for (int j = 0; j < 8; j++) {
                float p = 0.f;
#pragma unroll
                for (int i = 0; i < 8; i++)
                    p += s_wf[j][lane * 8 + i] * __ldg(&aw[lane * 8 + i]);
                p = wredsum(p);
                if (lane == 0) g_va[k0 + j] = p;
            }
        }
    } else {
        __shared__ float s_b[256];
        __shared__ float s_part[8];
        s_b[tid] = wfb[tid];
        __syncthreads();
        float acc = 0.f;
#pragma unroll 4
        for (int d = 0; d < 256; d++) acc += s_b[d] * w2[(size_t)d * D_ + tid];
        g_bias2[tid] = acc + atb[tid];
        float p = wredsum(s_b[tid] * __ldg(&aw[tid]));
        if (lane == 0) s_part[w] = p;
        __syncthreads();
        if (tid < 32) {
            float t = (tid < 8) ? s_part[tid] : 0.f;
            t = wredsum(t);
            if (tid == 0) g_ba = t + ab[0];
        }
    }
}

// ---------------- K1: gconv (10000) + lean splits (w1: 256, tgt: 512) -------
#define GC_W1  10000
#define GC_TGT 10256
#define GC_END 10768

__global__ void k_gconv(const float* __restrict__ emb, const int* __restrict__ cols,
                        const float* __restrict__ vals, const float* __restrict__ w1,
                        const float* __restrict__ tgt) {
    int bid = blockIdx.x;
    int tid = threadIdx.x;
    if (bid >= GC_W1) {
        if (bid < GC_TGT) {
            // W1 transpose + bf16 hi/lo split (lean)
            int f = (bid - GC_W1) * 256 + tid;  // 65536 total
            float a = w1[f];
            int k = f >> 8, n = f & 255;
            __nv_bfloat16 h = __float2bfloat16(a);
            float lo = a - __bfloat162float(h);
            g_w1t_hi[n * 256 + k] = h;
            g_w1t_lo[n * 256 + k] = __float2bfloat16(lo);
        } else {
            // tgt bf16 hi/lo split (lean)
            int f4 = ((bid - GC_TGT) * 256 + tid) * 4;
            float4 v = *(const float4*)&tgt[f4];
            uint2 hi, lo;
            split4(v, hi, lo);
            *(uint2*)&g_tg_hi[f4] = hi;
            *(uint2*)&g_tg_lo[f4] = lo;
        }
        return;
    }
    // graph conv: 4 nodes per block -> bf16 hi/lo
    int node = bid * 4 + (tid >> 6);
    int d4 = (tid & 63) << 2;
    float4 h = *(const float4*)&emb[(size_t)node * D_ + d4];
    int base = node * DEG_;
#pragma unroll
    for (int j = 0; j < DEG_; j++) {
        int c = __ldg(&cols[base + j]);
        float v = __ldg(&vals[base + j]);
        float4 e = *(const float4*)&emb[(size_t)c * D_ + d4];
        h.x += v * e.x;
        h.y += v * e.y;
        h.z += v * e.z;
        h.w += v * e.w;
    }
    h.x *= 0.5f; h.y *= 0.5f; h.z *= 0.5f; h.w *= 0.5f;
    size_t off = (size_t)node * D_ + d4;
    uint2 hi, lo;
    split4(h, hi, lo);
    *(uint2*)&g_a_hi[off] = hi;
    *(uint2*)&g_a_lo[off] = lo;
}

// ---------------- K2: GEMMs: G1 = gemb @ W1 (1250 blks) + t2 = tgt@Wc (32) --
#define GEMM_SMEM 98304
#define BUF_STRIDE 49152
#define GEMM_BLKS 1250
#define T2_BLKS 32

__device__ __forceinline__ void load_chunk(uint32_t sb, int tid, int row0, int n0, int kc,
                                           const __nv_bfloat16* __restrict__ Ah,
                                           const __nv_bfloat16* __restrict__ Al,
                                           const __nv_bfloat16* __restrict__ Bh,
                                           const __nv_bfloat16* __restrict__ Bl,
                                           int lda, int ldb) {
#pragma unroll
    for (int i = 0; i < 2; i++) {
        int idx = tid + i * 256;
        int r = idx >> 3, g = idx & 7;
        uint32_t soff = (uint32_t)(r * 128 + ((g ^ (r & 7)) << 4));
        size_t abase = (size_t)(row0 + r) * lda + kc * 64 + g * 8;
        cpa16(sb + soff,        Ah + abase);
        cpa16(sb + 8192 + soff, Al + abase);
    }
#pragma unroll
    for (int i = 0; i < 4; i++) {
        int idx = tid + i * 256;
        int r = idx >> 3, g = idx & 7;
        uint32_t soff = (uint32_t)(r * 128 + ((g ^ (r & 7)) << 4));
        size_t bbase = (size_t)(n0 + r) * ldb + kc * 64 + g * 8;
        cpa16(sb + 16384 + soff, Bh + bbase);
        cpa16(sb + 32768 + soff, Bl + bbase);
    }
    asm volatile("cp.async.commit_group;" ::: "memory");
}

__global__ __launch_bounds__(256, 2) void k_gemm() {
    extern __shared__ char sm[];
    uint32_t sbase = smem_u32(sm);
    int tid = threadIdx.x, lane = tid & 31, w = tid >> 5;
    int bid = blockIdx.x;

    const __nv_bfloat16 *Ah, *Al, *Bh, *Bl;
    int lda, ldb, nkc, row0, n0, isT2;
    if (bid < GEMM_BLKS) {
        Ah = g_a_hi; Al = g_a_lo; Bh = g_w1t_hi; Bl = g_w1t_lo;
        lda = 256; ldb = 256; nkc = 4; isT2 = 0;
        row0 = (bid >> 1) * 64; n0 = (bid & 1) * 128;
    } else {
        int t = bid - GEMM_BLKS;
        Ah = g_tg_hi; Al = g_tg_lo; Bh = g_wc_hi; Bl = g_wc_lo;
        lda = 512; ldb = 512; nkc = 8; isT2 = 1;
        row0 = (t >> 1) * 64; n0 = (t & 1) * 128;
    }

    int wm = w & 1, wn = w >> 1;          // 2m x 4n warps; warp tile 32m x 32n
    int quad = lane >> 3, ri = lane & 7;
    int arow_b = wm * 32 + ((quad & 1) << 3) + ri;
    int brow_b = wn * 32 + ((quad & 1) << 3) + ri;
    int gsel = quad >> 1;

    float acc[2][4][4];
#pragma unroll
    for (int i = 0; i < 2; i++)
#pragma unroll
        for (int j = 0; j < 4; j++)
#pragma unroll
            for (int q = 0; q < 4; q++) acc[i][j][q] = 0.f;

    load_chunk(sbase, tid, row0, n0, 0, Ah, Al, Bh, Bl, lda, ldb);

    for (int kc = 0; kc < nkc; kc++) {
        uint32_t sb = sbase + (kc & 1) * BUF_STRIDE;
        asm volatile("cp.async.wait_group 0;" ::: "memory");
        __syncthreads();
        if (kc < nkc - 1)
            load_chunk(sbase + ((kc + 1) & 1) * BUF_STRIDE, tid, row0, n0, kc + 1,
                       Ah, Al, Bh, Bl, lda, ldb);
#pragma unroll
        for (int ks = 0; ks < 4; ks++) {
            uint32_t ah[2][4], al[2][4], bh[2][4], bl[2][4];
            int gx = ((ks * 2 + gsel) ^ ri) << 4;
#pragma unroll
            for (int mt = 0; mt < 2; mt++) {
                uint32_t off = (uint32_t)((arow_b + mt * 16) * 128 + gx);
                ldsm4(ah[mt], sb + off);
                ldsm4(al[mt], sb + 8192 + off);
            }
#pragma unroll
            for (int pt = 0; pt < 2; pt++) {
                uint32_t off = (uint32_t)((brow_b + pt * 16) * 128 + gx);
                ldsm4(bh[pt], sb + 16384 + off);
                ldsm4(bl[pt], sb + 32768 + off);
            }
#pragma unroll
            for (int mt = 0; mt < 2; mt++) {
#pragma unroll
                for (int nt = 0; nt < 4; nt++) {
                    uint32_t b0h = bh[nt >> 1][nt & 1], b1h = bh[nt >> 1][(nt & 1) + 2];
                    uint32_t b0l = bl[nt >> 1][nt & 1], b1l = bl[nt >> 1][(nt & 1) + 2];
                    mma_bf16(acc[mt][nt], ah[mt], b0h, b1h);
                    mma_bf16(acc[mt][nt], ah[mt], b0l, b1l);
                    mma_bf16(acc[mt][nt], al[mt], b0h, b1h);
                }
            }
        }
    }

    int mrb = row0 + wm * 32 + (lane >> 2);
    int ncb = n0 + wn * 32 + (lane & 3) * 2;
    float* outp = isT2 ? g_t2 : g_G1;
#pragma unroll
    for (int mt = 0; mt < 2; mt++) {
#pragma unroll
        for (int nt = 0; nt < 4; nt++) {
            int m = mrb + mt * 16;
            int n = ncb + nt * 8;
            float2 v0 = make_float2(acc[mt][nt][0], acc[mt][nt][1]);
            float2 v1 = make_float2(acc[mt][nt][2], acc[mt][nt][3]);
            if (isT2) {
                float b0 = g_bias2[n], b1 = g_bias2[n + 1];
                v0.x += b0; v0.y += b1;
                v1.x += b0; v1.y += b1;
            }
            *(float2*)&outp[(size_t)m * D_ + n] = v0;
            *(float2*)&outp[(size_t)(m + 8) * D_ + n] = v1;
        }
    }
}

// ---------------- K3: fused scores + alpha + entmax + output (R10 exact) ----
// dynamic smem: hi rows [50][256] bf16 (25600 B) | lo rows (25600 B)
#define FIN_SMEM (2 * L_ * D_ * 2)
#define BIS_ITERS 34

__global__ void k_final(const int* __restrict__ items, const float* __restrict__ w0,
                        const float* __restrict__ tgt, float* __restrict__ out) {
    extern __shared__ __align__(16) char smd[];
    __shared__ __align__(16) float s_t2[256], s_w0[256];
    __shared__ float s_sc[64], s_attn[64];
    __shared__ int s_it[64];
    __shared__ float rs[8];
    int tid = threadIdx.x, lane = tid & 31, w = tid >> 5;
    int b = blockIdx.x;

    s_t2[tid] = g_t2[(size_t)b * D_ + tid];
    s_w0[tid] = w0[tid];
    if (tid < L_) s_it[tid] = items[b * L_ + tid];
    __syncthreads();

    // prefetch gemb hi/lo rows for the output stage (overlaps scores + entmax)
    uint32_t sdm = smem_u32(smd);
    for (int l = w; l < L_; l += 8) {
        int it = s_it[l];
        cpa16(sdm + l * 512 + lane * 16,         g_a_hi + (size_t)it * D_ + lane * 8);
        cpa16(sdm + 25600 + l * 512 + lane * 16, g_a_lo + (size_t)it * D_ + lane * 8);
    }
    asm volatile("cp.async.commit_group;" ::: "memory");

    // scores: warp per row, strided
    for (int l = w; l < L_; l += 8) {
        int it = s_it[l];
        const float* g = g_G1 + (size_t)it * D_ + lane * 8;
        float4 g0 = *(const float4*)g, g1 = *(const float4*)(g + 4);
        float4 t0 = *(const float4*)&s_t2[lane * 8], t1 = *(const float4*)&s_t2[lane * 8 + 4];
        float4 w0a = *(const float4*)&s_w0[lane * 8], w0b = *(const float4*)&s_w0[lane * 8 + 4];
        float acc = fmaxf(g0.x + t0.x, 0.f) * w0a.x + fmaxf(g0.y + t0.y, 0.f) * w0a.y +
                    fmaxf(g0.z + t0.z, 0.f) * w0a.z + fmaxf(g0.w + t0.w, 0.f) * w0a.w +
                    fmaxf(g1.x + t1.x, 0.f) * w0b.x + fmaxf(g1.y + t1.y, 0.f) * w0b.y +
                    fmaxf(g1.z + t1.z, 0.f) * w0b.z + fmaxf(g1.w + t1.w, 0.f) * w0b.w;
        acc = wredsum(acc);
        if (lane == 0) s_sc[l] = acc;
    }
    __syncthreads();

    // warp 0: alpha = sigmoid(tgt.va + ba) + 1, then entmax bisection
    if (w == 0) {
        float av = 0.f;
        const float* tp = tgt + (size_t)b * D2_ + lane * 16;
        const float* vp = g_va + lane * 16;
#pragma unroll
        for (int i = 0; i < 4; i++) {
            float4 tv = *(const float4*)(tp + i * 4);
            float4 vv = *(const float4*)(vp + i * 4);
            av += tv.x * vv.x + tv.y * vv.y + tv.z * vv.z + tv.w * vv.w;
        }
        av = wredsum(av);
        float x = av + g_ba;
        float alpha = 1.f / (1.f + expf(-x)) + 1.f;
        if (alpha == 1.f) alpha = 1.00001f;

        float am1 = alpha - 1.f;
        float inv = 1.f / am1;
        float Xa0 = s_sc[lane] * am1;
        float Xa1 = (lane < L_ - 32) ? s_sc[32 + lane] * am1 : -CUDART_INF_F;

        float m = wredmax(fmaxf(Xa0, Xa1));
        float tau_lo = m - 1.f;
        float tau_hi = m - powf(1.f / (float)L_, am1);
        float f_lo = wredsum(fpow(Xa0 - tau_lo, inv) + fpow(Xa1 - tau_lo, inv)) - 1.f;

        float dm = tau_hi - tau_lo;
        float tau_m = tau_lo;
        for (int it = 0; it < BIS_ITERS; it++) {
            dm *= 0.5f;
            tau_m = tau_lo + dm;
            float fm = wredsum(fpow(Xa0 - tau_m, inv) + fpow(Xa1 - tau_m, inv)) - 1.f;
            if (fm * f_lo >= 0.f) tau_lo = tau_m;
        }
        float p0 = fpow(Xa0 - tau_m, inv);
        float p1 = fpow(Xa1 - tau_m, inv);
        float s = wredsum(p0 + p1);
        s_attn[lane] = p0 / s;
        if (lane < L_ - 32) s_attn[32 + lane] = p1 / s;
    }
    asm volatile("cp.async.wait_group 0;" ::: "memory");
    __syncthreads();

    // output: c = attn^T (hi+lo rows in smem); selu; L2-normalize
    const __nv_bfloat16* ph = (const __nv_bfloat16*)smd;
    const __nv_bfloat16* pl = (const __nv_bfloat16*)(smd + 25600);
    float accd = 0.f;
#pragma unroll
    for (int l = 0; l < L_; l++) {
        float v = __bfloat162float(ph[l * 256 + tid]) + __bfloat162float(pl[l * 256 + tid]);
        accd += s_attn[l] * v;
    }
    const float SC = 1.0507009873554805f;
    const float AL = 1.6732632423543772f;
    float v = accd > 0.f ? SC * accd : SC * AL * expm1f(accd);
    float sq = wredsum(v * v);
    if (lane == 0) rs[w] = sq;
    __syncthreads();
    if (tid < 32) {
        float t = (tid < 8) ? rs[tid] : 0.f;
        t = wredsum(t);
        if (tid == 0) rs[0] = t;
    }
    __syncthreads();
    out[(size_t)b * D_ + tid] = v / sqrtf(rs[0]);
}

// ---------------- launch ------------------------------------------------------
extern "C" void kernel_launch(void* const* d_in, const int* in_sizes, int n_in,
                              void* d_out, int out_size) {
    const int* items = (const int*)d_in[0];
    const float* tgt = (const float*)d_in[3];
    const float* emb = (const float*)d_in[4];
    const int* acols = (const int*)d_in[6];
    const float* avals = (const float*)d_in[7];
    const float* wfw = (const float*)d_in[8];
    const float* wfb = (const float*)d_in[9];
    const float* aww = (const float*)d_in[10];
    const float* awb = (const float*)d_in[11];
    const float* w0 = (const float*)d_in[12];
    const float* w1 = (const float*)d_in[13];
    const float* w2 = (const float*)d_in[14];
    const float* abias = (const float*)d_in[15];
    float* out = (float*)d_out;

    cudaFuncSetAttribute(k_gemm, cudaFuncAttributeMaxDynamicSharedMemorySize, GEMM_SMEM);
    cudaFuncSetAttribute(k_final, cudaFuncAttributeMaxDynamicSharedMemorySize, FIN_SMEM);

    k_prep2<<<P2_B2 + 1, 256>>>(w2, wfw, wfb, aww, awb, abias);
    k_gconv<<<GC_END, 256>>>(emb, acols, avals, w1, tgt);
    k_gemm<<<GEMM_BLKS + T2_BLKS, 256, GEMM_SMEM>>>();
    k_final<<<B_, 256, FIN_SMEM>>>(items, w0, tgt, out);
}

// round 17
// speedup vs baseline: 1.0891x; 1.0587x over previous
#include <cuda_runtime.h>
#include <cuda_bf16.h>
#include <math_constants.h>
#include <cstdint>

#define B_   1024
#define L_   50
#define D_   256
#define D2_  512
#define DEG_ 12
#define BL_  (B_ * L_)   // 51200
#define GM_  40000       // number of graph nodes

// ---------------- scratch (device globals; no allocations allowed) ----------
__device__ __align__(16) float g_t2[B_ * D_];
__device__ __align__(16) __nv_bfloat16 g_a_hi[(size_t)GM_ * D_];   // graph_embs hi
__device__ __align__(16) __nv_bfloat16 g_a_lo[(size_t)GM_ * D_];   // graph_embs lo
__device__ __align__(16) float g_G1[(size_t)GM_ * D_];             // graph_embs @ W1
__device__ __align__(16) __nv_bfloat16 g_w1t_hi[D_ * D_];          // W1^T hi [n][k]
__device__ __align__(16) __nv_bfloat16 g_w1t_lo[D_ * D_];          // W1^T lo [n][k]
__device__ __align__(16) __nv_bfloat16 g_tg_hi[B_ * D2_];          // tgt hi [b][k]
__device__ __align__(16) __nv_bfloat16 g_tg_lo[B_ * D2_];          // tgt lo
__device__ __align__(16) __nv_bfloat16 g_wc_hi[D_ * D2_];          // Wc^T hi [n][k]
__device__ __align__(16) __nv_bfloat16 g_wc_lo[D_ * D2_];          // Wc^T lo
__device__ __align__(16) float g_va[D2_];                          // wfw^T @ aw
__device__ __align__(16) float g_bias2[D_];                        // wfb@w2 + at_bias
__device__ float g_ba;                                             // wfb.aw + ab

// ---------------- small helpers ---------------------------------------------
__device__ __forceinline__ float wredsum(float v) {
#pragma unroll
    for (int o = 16; o > 0; o >>= 1) v += __shfl_xor_sync(0xFFFFFFFFu, v, o);
    return v;
}
__device__ __forceinline__ float wredmax(float v) {
#pragma unroll
    for (int o = 16; o > 0; o >>= 1) v = fmaxf(v, __shfl_xor_sync(0xFFFFFFFFu, v, o));
    return v;
}
__device__ __forceinline__ uint32_t smem_u32(const void* p) {
    uint32_t a;
    asm("{ .reg .u64 t; cvta.to.shared.u64 t, %1; cvt.u32.u64 %0, t; }" : "=r"(a) : "l"(p));
    return a;
}
__device__ __forceinline__ uint32_t pk2(__nv_bfloat16 a, __nv_bfloat16 b) {
    __nv_bfloat162 p(a, b);
    return *(uint32_t*)&p;
}
__device__ __forceinline__ void split4(float4 v, uint2& hi, uint2& lo) {
    __nv_bfloat16 h0 = __float2bfloat16(v.x), h1 = __float2bfloat16(v.y);
    __nv_bfloat16 h2 = __float2bfloat16(v.z), h3 = __float2bfloat16(v.w);
    __nv_bfloat16 l0 = __float2bfloat16(v.x - __bfloat162float(h0));
    __nv_bfloat16 l1 = __float2bfloat16(v.y - __bfloat162float(h1));
    __nv_bfloat16 l2 = __float2bfloat16(v.z - __bfloat162float(h2));
    __nv_bfloat16 l3 = __float2bfloat16(v.w - __bfloat162float(h3));
    hi = make_uint2(pk2(h0, h1), pk2(h2, h3));
    lo = make_uint2(pk2(l0, l1), pk2(l2, l3));
}
__device__ __forceinline__ void cpa16(uint32_t dst, const void* src) {
    asm volatile("cp.async.cg.shared.global [%0], [%1], 16;" :: "r"(dst), "l"(src));
}
__device__ __forceinline__ void ldsm4(uint32_t* r, uint32_t addr) {
    asm volatile("ldmatrix.sync.aligned.m8n8.x4.shared.b16 {%0,%1,%2,%3}, [%4];"
                 : "=r"(r[0]), "=r"(r[1]), "=r"(r[2]), "=r"(r[3]) : "r"(addr));
}
__device__ __forceinline__ void mma_bf16(float* c, const uint32_t* a, uint32_t b0, uint32_t b1) {
    asm volatile(
        "mma.sync.aligned.m16n8k16.row.col.f32.bf16.bf16.f32 "
        "{%0,%1,%2,%3}, {%4,%5,%6,%7}, {%8,%9}, {%0,%1,%2,%3};"
        : "+f"(c[0]), "+f"(c[1]), "+f"(c[2]), "+f"(c[3])
        : "r"(a[0]), "r"(a[1]), "r"(a[2]), "r"(a[3]), "r"(b0), "r"(b1));
}
// fast z^inv for z >= 0 (lg2(0) = -inf -> ex2(-inf) = 0, matching max(z,0)^inv)
__device__ __forceinline__ float fpow(float z, float inv) {
    z = fmaxf(z, 0.f);
    float l, r;
    asm("lg2.approx.f32 %0, %1;" : "=f"(l) : "f"(z));
    l *= inv;
    asm("ex2.approx.f32 %0, %1;" : "=f"(r) : "f"(l));
    return r;
}

// ---------------- K0: prep2 — Wc (+va) and bias2 (+ba), 65 blocks -----------
#define P2_B2 64     // [0,64) Wc+va (8 k each) | 64 bias2+ba

__global__ void k_prep2(const float* __restrict__ w2, const float* __restrict__ wfw,
                        const float* __restrict__ wfb, const float* __restrict__ aw,
                        const float* __restrict__ ab, const float* __restrict__ atb) {
    int bid = blockIdx.x;
    int tid = threadIdx.x;
    int lane = tid & 31, w = tid >> 5;

    if (bid < P2_B2) {
        int k0 = bid * 8;
        __shared__ float s_wf[8][256];   // s_wf[j][d] = wfw[d][k0+j]
        {
            float4 a = *(const float4*)&wfw[(size_t)tid * D2_ + k0];
            float4 b = *(const float4*)&wfw[(size_t)tid * D2_ + k0 + 4];
            s_wf[0][tid] = a.x; s_wf[1][tid] = a.y;
            s_wf[2][tid] = a.z; s_wf[3][tid] = a.w;
            s_wf[4][tid] = b.x; s_wf[5][tid] = b.y;
            s_wf[6][tid] = b.z; s_wf[7][tid] = b.w;
        }
        __syncthreads();
        float acc[8];
#pragma unroll
        for (int j = 0; j < 8; j++) acc[j] = 0.f;
#pragma unroll 4
        for (int d = 0; d < 256; d++) {
            float wv = w2[(size_t)d * D_ + tid];
#pragma unroll
            for (int j = 0; j < 8; j++) acc[j] += s_wf[j][d] * wv;
        }
#pragma unroll
        for (int j = 0; j < 8; j++) {
            __nv_bfloat16 h = __float2bfloat16(acc[j]);
            float lo = acc[j] - __bfloat162float(h);
            g_wc_hi[(size_t)tid * D2_ + k0 + j] = h;
            g_wc_lo[(size_t)tid * D2_ + k0 + j] = __float2bfloat16(lo);
        }
        if (w == 0) {
#pragma unroll
            for (int j = 0; j < 8; j++) {
                float p = 0.f;
#pragma unroll
                for (int i = 0; i < 8; i++)
                    p += s_wf[j][lane * 8 + i] * __ldg(&aw[lane * 8 + i]);
                p = wredsum(p);
                if (lane == 0) g_va[k0 + j] = p;
            }
        }
    } else {
        __shared__ float s_b[256];
        __shared__ float s_part[8];
        s_b[tid] = wfb[tid];
        __syncthreads();
        float acc = 0.f;
#pragma unroll 4
        for (int d = 0; d < 256; d++) acc += s_b[d] * w2[(size_t)d * D_ + tid];
        g_bias2[tid] = acc + atb[tid];
        float p = wredsum(s_b[tid] * __ldg(&aw[tid]));
        if (lane == 0) s_part[w] = p;
        __syncthreads();
        if (tid < 32) {
            float t = (tid < 8) ? s_part[tid] : 0.f;
            t = wredsum(t);
            if (tid == 0) g_ba = t + ab[0];
        }
    }
}

// ---------------- K1: gconv (10000) + lean splits (w1: 256, tgt: 512) -------
#define GC_W1  10000
#define GC_TGT 10256
#define GC_END 10768

__global__ void k_gconv(const float* __restrict__ emb, const int* __restrict__ cols,
                        const float* __restrict__ vals, const float* __restrict__ w1,
                        const float* __restrict__ tgt) {
    int bid = blockIdx.x;
    int tid = threadIdx.x;
    if (bid >= GC_W1) {
        if (bid < GC_TGT) {
            // W1 transpose + bf16 hi/lo split (lean)
            int f = (bid - GC_W1) * 256 + tid;  // 65536 total
            float a = w1[f];
            int k = f >> 8, n = f & 255;
            __nv_bfloat16 h = __float2bfloat16(a);
            float lo = a - __bfloat162float(h);
            g_w1t_hi[n * 256 + k] = h;
            g_w1t_lo[n * 256 + k] = __float2bfloat16(lo);
        } else {
            // tgt bf16 hi/lo split (lean)
            int f4 = ((bid - GC_TGT) * 256 + tid) * 4;
            float4 v = *(const float4*)&tgt[f4];
            uint2 hi, lo;
            split4(v, hi, lo);
            *(uint2*)&g_tg_hi[f4] = hi;
            *(uint2*)&g_tg_lo[f4] = lo;
        }
        return;
    }
    // graph conv: 4 nodes per block -> bf16 hi/lo
    int node = bid * 4 + (tid >> 6);
    int d4 = (tid & 63) << 2;
    float4 h = *(const float4*)&emb[(size_t)node * D_ + d4];
    int base = node * DEG_;
#pragma unroll
    for (int j = 0; j < DEG_; j++) {
        int c = __ldg(&cols[base + j]);
        float v = __ldg(&vals[base + j]);
        float4 e = *(const float4*)&emb[(size_t)c * D_ + d4];
        h.x += v * e.x;
        h.y += v * e.y;
        h.z += v * e.z;
        h.w += v * e.w;
    }
    h.x *= 0.5f; h.y *= 0.5f; h.z *= 0.5f; h.w *= 0.5f;
    size_t off = (size_t)node * D_ + d4;
    uint2 hi, lo;
    split4(h, hi, lo);
    *(uint2*)&g_a_hi[off] = hi;
    *(uint2*)&g_a_lo[off] = lo;
}

// ---------------- K2: GEMMs. t2 blocks FIRST (long blocks scheduled early) --
// bid [0,32): t2 = tgt @ Wc (K=512, 8 chunks)  |  bid [32,1282): G1 (K=256)
#define GEMM_SMEM 98304
#define BUF_STRIDE 49152
#define GEMM_BLKS 1250
#define T2_BLKS 32

__device__ __forceinline__ void load_chunk(uint32_t sb, int tid, int row0, int n0, int kc,
                                           const __nv_bfloat16* __restrict__ Ah,
                                           const __nv_bfloat16* __restrict__ Al,
                                           const __nv_bfloat16* __restrict__ Bh,
                                           const __nv_bfloat16* __restrict__ Bl,
                                           int lda, int ldb) {
#pragma unroll
    for (int i = 0; i < 2; i++) {
        int idx = tid + i * 256;
        int r = idx >> 3, g = idx & 7;
        uint32_t soff = (uint32_t)(r * 128 + ((g ^ (r & 7)) << 4));
        size_t abase = (size_t)(row0 + r) * lda + kc * 64 + g * 8;
        cpa16(sb + soff,        Ah + abase);
        cpa16(sb + 8192 + soff, Al + abase);
    }
#pragma unroll
    for (int i = 0; i < 4; i++) {
        int idx = tid + i * 256;
        int r = idx >> 3, g = idx & 7;
        uint32_t soff = (uint32_t)(r * 128 + ((g ^ (r & 7)) << 4));
        size_t bbase = (size_t)(n0 + r) * ldb + kc * 64 + g * 8;
        cpa16(sb + 16384 + soff, Bh + bbase);
        cpa16(sb + 32768 + soff, Bl + bbase);
    }
    asm volatile("cp.async.commit_group;" ::: "memory");
}

__global__ __launch_bounds__(256, 2) void k_gemm() {
    extern __shared__ char sm[];
    uint32_t sbase = smem_u32(sm);
    int tid = threadIdx.x, lane = tid & 31, w = tid >> 5;
    int bid = blockIdx.x;

    const __nv_bfloat16 *Ah, *Al, *Bh, *Bl;
    int lda, ldb, nkc, row0, n0, isT2;
    if (bid < T2_BLKS) {
        // long blocks first: better wave packing
        Ah = g_tg_hi; Al = g_tg_lo; Bh = g_wc_hi; Bl = g_wc_lo;
        lda = 512; ldb = 512; nkc = 8; isT2 = 1;
        row0 = (bid >> 1) * 64; n0 = (bid & 1) * 128;
    } else {
        int t = bid - T2_BLKS;
        Ah = g_a_hi; Al = g_a_lo; Bh = g_w1t_hi; Bl = g_w1t_lo;
        lda = 256; ldb = 256; nkc = 4; isT2 = 0;
        row0 = (t >> 1) * 64; n0 = (t & 1) * 128;
    }

    int wm = w & 1, wn = w >> 1;          // 2m x 4n warps; warp tile 32m x 32n
    int quad = lane >> 3, ri = lane & 7;
    int arow_b = wm * 32 + ((quad & 1) << 3) + ri;
    int brow_b = wn * 32 + ((quad & 1) << 3) + ri;
    int gsel = quad >> 1;

    float acc[2][4][4];
#pragma unroll
    for (int i = 0; i < 2; i++)
#pragma unroll
        for (int j = 0; j < 4; j++)
#pragma unroll
            for (int q = 0; q < 4; q++) acc[i][j][q] = 0.f;

    load_chunk(sbase, tid, row0, n0, 0, Ah, Al, Bh, Bl, lda, ldb);

    for (int kc = 0; kc < nkc; kc++) {
        uint32_t sb = sbase + (kc & 1) * BUF_STRIDE;
        asm volatile("cp.async.wait_group 0;" ::: "memory");
        __syncthreads();
        if (kc < nkc - 1)
            load_chunk(sbase + ((kc + 1) & 1) * BUF_STRIDE, tid, row0, n0, kc + 1,
                       Ah, Al, Bh, Bl, lda, ldb);
#pragma unroll
        for (int ks = 0; ks < 4; ks++) {
            uint32_t ah[2][4], al[2][4], bh[2][4], bl[2][4];
            int gx = ((ks * 2 + gsel) ^ ri) << 4;
#pragma unroll
            for (int mt = 0; mt < 2; mt++) {
                uint32_t off = (uint32_t)((arow_b + mt * 16) * 128 + gx);
                ldsm4(ah[mt], sb + off);
                ldsm4(al[mt], sb + 8192 + off);
            }
#pragma unroll
            for (int pt = 0; pt < 2; pt++) {
                uint32_t off = (uint32_t)((brow_b + pt * 16) * 128 + gx);
                ldsm4(bh[pt], sb + 16384 + off);
                ldsm4(bl[pt], sb + 32768 + off);
            }
#pragma unroll
            for (int mt = 0; mt < 2; mt++) {
#pragma unroll
                for (int nt = 0; nt < 4; nt++) {
                    uint32_t b0h = bh[nt >> 1][nt & 1], b1h = bh[nt >> 1][(nt & 1) + 2];
                    uint32_t b0l = bl[nt >> 1][nt & 1], b1l = bl[nt >> 1][(nt & 1) + 2];
                    mma_bf16(acc[mt][nt], ah[mt], b0h, b1h);
                    mma_bf16(acc[mt][nt], ah[mt], b0l, b1l);
                    mma_bf16(acc[mt][nt], al[mt], b0h, b1h);
                }
            }
        }
    }

    int mrb = row0 + wm * 32 + (lane >> 2);
    int ncb = n0 + wn * 32 + (lane & 3) * 2;
    float* outp = isT2 ? g_t2 : g_G1;
#pragma unroll
    for (int mt = 0; mt < 2; mt++) {
#pragma unroll
        for (int nt = 0; nt < 4; nt++) {
            int m = mrb + mt * 16;
            int n = ncb + nt * 8;
            float2 v0 = make_float2(acc[mt][nt][0], acc[mt][nt][1]);
            float2 v1 = make_float2(acc[mt][nt][2], acc[mt][nt][3]);
            if (isT2) {
                float b0 = g_bias2[n], b1 = g_bias2[n + 1];
                v0.x += b0; v0.y += b1;
                v1.x += b0; v1.y += b1;
            }
            *(float2*)&outp[(size_t)m * D_ + n] = v0;
            *(float2*)&outp[(size_t)(m + 8) * D_ + n] = v1;
        }
    }
}

// ---------------- K3: fused scores + alpha + entmax + output ---------------
// dynamic smem: hi rows [50][256] bf16 (25600 B) | lo rows (25600 B)
#define FIN_SMEM (2 * L_ * D_ * 2)
#define BIS_ITERS 26   // dm < ulp(tau) beyond ~25 iters: further iters are bit-frozen

__global__ void k_final(const int* __restrict__ items, const float* __restrict__ w0,
                        const float* __restrict__ tgt, float* __restrict__ out) {
    extern __shared__ __align__(16) char smd[];
    __shared__ __align__(16) float s_t2[256], s_w0[256];
    __shared__ float s_sc[64], s_attn[64];
    __shared__ int s_it[64];
    __shared__ float rs[8];
    int tid = threadIdx.x, lane = tid & 31, w = tid >> 5;
    int b = blockIdx.x;

    s_t2[tid] = g_t2[(size_t)b * D_ + tid];
    s_w0[tid] = w0[tid];
    if (tid < L_) s_it[tid] = items[b * L_ + tid];
    __syncthreads();

    // prefetch gemb hi/lo rows for the output stage (overlaps scores + entmax)
    uint32_t sdm = smem_u32(smd);
    for (int l = w; l < L_; l += 8) {
        int it = s_it[l];
        cpa16(sdm + l * 512 + lane * 16,         g_a_hi + (size_t)it * D_ + lane * 8);
        cpa16(sdm + 25600 + l * 512 + lane * 16, g_a_lo + (size_t)it * D_ + lane * 8);
    }
    asm volatile("cp.async.commit_group;" ::: "memory");

    // scores: warp per row, strided
    for (int l = w; l < L_; l += 8) {
        int it = s_it[l];
        const float* g = g_G1 + (size_t)it * D_ + lane * 8;
        float4 g0 = *(const float4*)g, g1 = *(const float4*)(g + 4);
        float4 t0 = *(const float4*)&s_t2[lane * 8], t1 = *(const float4*)&s_t2[lane * 8 + 4];
        float4 w0a = *(const float4*)&s_w0[lane * 8], w0b = *(const float4*)&s_w0[lane * 8 + 4];
        float acc = fmaxf(g0.x + t0.x, 0.f) * w0a.x + fmaxf(g0.y + t0.y, 0.f) * w0a.y +
                    fmaxf(g0.z + t0.z, 0.f) * w0a.z + fmaxf(g0.w + t0.w, 0.f) * w0a.w +
                    fmaxf(g1.x + t1.x, 0.f) * w0b.x + fmaxf(g1.y + t1.y, 0.f) * w0b.y +
                    fmaxf(g1.z + t1.z, 0.f) * w0b.z + fmaxf(g1.w + t1.w, 0.f) * w0b.w;
        acc = wredsum(acc);
        if (lane == 0) s_sc[l] = acc;
    }
    __syncthreads();

    // warp 0: alpha = sigmoid(tgt.va + ba) + 1, then entmax bisection
    if (w == 0) {
        float av = 0.f;
        const float* tp = tgt + (size_t)b * D2_ + lane * 16;
        const float* vp = g_va + lane * 16;
#pragma unroll
        for (int i = 0; i < 4; i++) {
            float4 tv = *(const float4*)(tp + i * 4);
            float4 vv = *(const float4*)(vp + i * 4);
            av += tv.x * vv.x + tv.y * vv.y + tv.z * vv.z + tv.w * vv.w;
        }
        av = wredsum(av);
        float x = av + g_ba;
        float alpha = 1.f / (1.f + expf(-x)) + 1.f;
        if (alpha == 1.f) alpha = 1.00001f;

        float am1 = alpha - 1.f;
        float inv = 1.f / am1;
        float Xa0 = s_sc[lane] * am1;
        float Xa1 = (lane < L_ - 32) ? s_sc[32 + lane] * am1 : -CUDART_INF_F;

        float m = wredmax(fmaxf(Xa0, Xa1));
        float tau_lo = m - 1.f;
        float tau_hi = m - powf(1.f / (float)L_, am1);
        float f_lo = wredsum(fpow(Xa0 - tau_lo, inv) + fpow(Xa1 - tau_lo, inv)) - 1.f;

        float dm = tau_hi - tau_lo;
        float tau_m = tau_lo;
        for (int it = 0; it < BIS_ITERS; it++) {
            dm *= 0.5f;
            tau_m = tau_lo + dm;
            float fm = wredsum(fpow(Xa0 - tau_m, inv) + fpow(Xa1 - tau_m, inv)) - 1.f;
            if (fm * f_lo >= 0.f) tau_lo = tau_m;
        }
        float p0 = fpow(Xa0 - tau_m, inv);
        float p1 = fpow(Xa1 - tau_m, inv);
        float s = wredsum(p0 + p1);
        s_attn[lane] = p0 / s;
        if (lane < L_ - 32) s_attn[32 + lane] = p1 / s;
    }
    asm volatile("cp.async.wait_group 0;" ::: "memory");
    __syncthreads();

    // output: c = attn^T (hi+lo rows in smem); selu; L2-normalize
    const __nv_bfloat16* ph = (const __nv_bfloat16*)smd;
    const __nv_bfloat16* pl = (const __nv_bfloat16*)(smd + 25600);
    float accd = 0.f;
#pragma unroll
    for (int l = 0; l < L_; l++) {
        float v = __bfloat162float(ph[l * 256 + tid]) + __bfloat162float(pl[l * 256 + tid]);
        accd += s_attn[l] * v;
    }
    const float SC = 1.0507009873554805f;
    const float AL = 1.6732632423543772f;
    float v = accd > 0.f ? SC * accd : SC * AL * expm1f(accd);
    float sq = wredsum(v * v);
    if (lane == 0) rs[w] = sq;
    __syncthreads();
    if (tid < 32) {
        float t = (tid < 8) ? rs[tid] : 0.f;
        t = wredsum(t);
        if (tid == 0) rs[0] = t;
    }
    __syncthreads();
    out[(size_t)b * D_ + tid] = v / sqrtf(rs[0]);
}

// ---------------- launch ------------------------------------------------------
extern "C" void kernel_launch(void* const* d_in, const int* in_sizes, int n_in,
                              void* d_out, int out_size) {
    const int* items = (const int*)d_in[0];
    const float* tgt = (const float*)d_in[3];
    const float* emb = (const float*)d_in[4];
    const int* acols = (const int*)d_in[6];
    const float* avals = (const float*)d_in[7];
    const float* wfw = (const float*)d_in[8];
    const float* wfb = (const float*)d_in[9];
    const float* aww = (const float*)d_in[10];
    const float* awb = (const float*)d_in[11];
    const float* w0 = (const float*)d_in[12];
    const float* w1 = (const float*)d_in[13];
    const float* w2 = (const float*)d_in[14];
    const float* abias = (const float*)d_in[15];
    float* out = (float*)d_out;

    cudaFuncSetAttribute(k_gemm, cudaFuncAttributeMaxDynamicSharedMemorySize, GEMM_SMEM);
    cudaFuncSetAttribute(k_final, cudaFuncAttributeMaxDynamicSharedMemorySize, FIN_SMEM);

    k_prep2<<<P2_B2 + 1, 256>>>(w2, wfw, wfb, aww, awb, abias);
    k_gconv<<<GC_END, 256>>>(emb, acols, avals, w1, tgt);
    k_gemm<<<GEMM_BLKS + T2_BLKS, 256, GEMM_SMEM>>>();
    k_final<<<B_, 256, FIN_SMEM>>>(items, w0, tgt, out);
}